// round 4
// baseline (speedup 1.0000x reference)
#include <cuda_runtime.h>
#include <cstdint>

// Problem constants
#define BB 4
#define SS 1024
#define DD 512
#define HH 8
#define DKK 64
#define BSD (BB*SS*DD)   // 2097152
#define TQ 8             // query rows per attention CTA
#define CK 128           // keys per attention chunk

// ---------------- scratch (device globals; no allocation) ----------------
__device__ float g_bufQ[2][BSD];
__device__ float g_bufK[2][BSD];
__device__ float g_bufV[2][BSD];
__device__ float g_bufO[2][BSD];

// ---------------- packed f32x2 helpers ----------------
__device__ __forceinline__ unsigned long long pack2(float lo, float hi) {
    unsigned long long r;
    asm("mov.b64 %0, {%1, %2};" : "=l"(r) : "f"(lo), "f"(hi));
    return r;
}
__device__ __forceinline__ void ffma2(unsigned long long& d,
                                      unsigned long long a, unsigned long long b) {
    asm("fma.rn.f32x2 %0, %1, %2, %0;" : "+l"(d) : "l"(a), "l"(b));
}
__device__ __forceinline__ float2 unpack2(unsigned long long v) {
    float2 f;
    asm("mov.b64 {%0, %1}, %2;" : "=f"(f.x), "=f"(f.y) : "l"(v));
    return f;
}

// ---------------- batched GEMM: C = A[4096,512] @ W[512,512] + bias ----------------
struct GB  { const float* A; const float* W; const float* bias; float* C; };
struct GB8 { GB g[8]; };

#define GM 128
#define GN 128
#define GK 8

__global__ __launch_bounds__(256, 2)
void gemm_batch_kernel(GB8 args) {
    const GB p = args.g[blockIdx.z];

    __shared__ __align__(16) unsigned long long As2[2][GK][GM]; // (a,a) pairs, 8KB each
    __shared__ __align__(16) float Ws[2][GK][GN];               // 4KB each

    const int tid = threadIdx.x;
    const int ty = tid >> 4;         // m-group 0..15
    const int tx = tid & 15;         // n-group 0..15
    const int m0 = blockIdx.y * GM;
    const int n0 = blockIdx.x * GN;

    // loaders
    const int lm  = tid >> 1;        // A row 0..127
    const int lkd = tid & 1;         // A k half (k quad offset)
    const int lk  = tid >> 5;        // W row 0..7
    const int lnq = tid & 31;        // W col quad 0..31

    const float* Aptr = p.A + (size_t)(m0 + lm) * 512 + lkd * 4;
    const float* Wptr = p.W + (size_t)lk * 512 + n0 + lnq * 4;

    float4 a4 = *(const float4*)Aptr;
    float4 w4 = *(const float4*)Wptr;
    As2[0][lkd * 4 + 0][lm] = pack2(a4.x, a4.x);
    As2[0][lkd * 4 + 1][lm] = pack2(a4.y, a4.y);
    As2[0][lkd * 4 + 2][lm] = pack2(a4.z, a4.z);
    As2[0][lkd * 4 + 3][lm] = pack2(a4.w, a4.w);
    *(float4*)&Ws[0][lk][lnq * 4] = w4;
    __syncthreads();

    unsigned long long acc[8][4];
    #pragma unroll
    for (int i = 0; i < 8; i++)
        #pragma unroll
        for (int j = 0; j < 4; j++) acc[i][j] = 0ull;

    int buf = 0;
    for (int k0 = 0; k0 < 512; k0 += GK) {
        const bool more = (k0 + GK) < 512;
        if (more) {
            a4 = *(const float4*)(Aptr + k0 + GK);
            w4 = *(const float4*)(Wptr + (size_t)(k0 + GK) * 512);
        }
        #pragma unroll
        for (int k = 0; k < GK; k++) {
            unsigned long long a2[8];
            #pragma unroll
            for (int ii = 0; ii < 4; ii++) {
                ulonglong2 av = *(const ulonglong2*)&As2[buf][k][ty * 8 + ii * 2];
                a2[ii * 2]     = av.x;
                a2[ii * 2 + 1] = av.y;
            }
            ulonglong2 wp0 = *(const ulonglong2*)&Ws[buf][k][tx * 8];
            ulonglong2 wp1 = *(const ulonglong2*)&Ws[buf][k][tx * 8 + 4];
            #pragma unroll
            for (int i = 0; i < 8; i++) {
                ffma2(acc[i][0], a2[i], wp0.x);
                ffma2(acc[i][1], a2[i], wp0.y);
                ffma2(acc[i][2], a2[i], wp1.x);
                ffma2(acc[i][3], a2[i], wp1.y);
            }
        }
        if (more) {
            int nb = buf ^ 1;
            As2[nb][lkd * 4 + 0][lm] = pack2(a4.x, a4.x);
            As2[nb][lkd * 4 + 1][lm] = pack2(a4.y, a4.y);
            As2[nb][lkd * 4 + 2][lm] = pack2(a4.z, a4.z);
            As2[nb][lkd * 4 + 3][lm] = pack2(a4.w, a4.w);
            *(float4*)&Ws[nb][lk][lnq * 4] = w4;
        }
        __syncthreads();
        buf ^= 1;
    }

    float4 b0 = *(const float4*)(p.bias + n0 + tx * 8);
    float4 b1 = *(const float4*)(p.bias + n0 + tx * 8 + 4);
    #pragma unroll
    for (int i = 0; i < 8; i++) {
        float2 p0 = unpack2(acc[i][0]);
        float2 p1 = unpack2(acc[i][1]);
        float2 p2 = unpack2(acc[i][2]);
        float2 p3 = unpack2(acc[i][3]);
        float4 o0, o1;
        o0.x = p0.x + b0.x; o0.y = p0.y + b0.y; o0.z = p1.x + b0.z; o0.w = p1.y + b0.w;
        o1.x = p2.x + b1.x; o1.y = p2.y + b1.y; o1.z = p3.x + b1.z; o1.w = p3.y + b1.w;
        float* Crow = p.C + (size_t)(m0 + ty * 8 + i) * 512 + n0 + tx * 8;
        *(float4*)Crow = o0;
        *(float4*)(Crow + 4) = o1;
    }
}

// ---------------- attention ----------------
__device__ __forceinline__ float warpReduceSum(float v) {
    #pragma unroll
    for (int o = 16; o > 0; o >>= 1) v += __shfl_xor_sync(0xffffffffu, v, o);
    return v;
}
__device__ __forceinline__ float warpReduceMax(float v) {
    #pragma unroll
    for (int o = 16; o > 0; o >>= 1) v = fmaxf(v, __shfl_xor_sync(0xffffffffu, v, o));
    return v;
}

// dynamic smem layout (floats):
//   s_sc   [8][1024]       8192
//   s_q    [8][64]          512
//   s_kv   [128][68]       8704   (phase 2 aliases first 8192 as cumsum scratch)
//   s_part [8][8][64]      4096
//   s_rsum [8]                8
#define SMEM_ATTN_FLOATS (8192 + 512 + 8704 + 4096 + 8)

__global__ __launch_bounds__(256, 2)
void attn_kernel(const float* __restrict__ gammas) {
    extern __shared__ float sm[];
    float* s_sc   = sm;               // [r*1024 + j]
    float* s_q    = sm + 8192;        // [r*64 + d]
    float* s_kv   = sm + 8704;        // [j*68 + d]
    float* s_cum  = sm + 8704;        // aliases s_kv during phase 2
    float* s_part = sm + 17408;       // [(s*8 + r)*64 + d]
    float* s_rsum = sm + 21504;

    const int q0 = blockIdx.x * TQ;
    const int bh = blockIdx.y;
    const int b  = bh >> 3;
    const int h  = bh & 7;
    const int st = blockIdx.z;

    const int tid  = threadIdx.x;
    const int lane = tid & 31;
    const int w    = tid >> 5;          // warp 0..7

    const float* __restrict__ Qbase = g_bufQ[st] + ((size_t)(b * SS + q0)) * DD + h * DKK;
    const float* __restrict__ Kbase = g_bufK[st] + (size_t)b * SS * DD + h * DKK;
    const float* __restrict__ Vbase = g_bufV[st] + (size_t)b * SS * DD + h * DKK;

    // load Q tile (8x64)
    if (tid < 128) {
        int r = tid >> 4, dq = tid & 15;
        *(float4*)&s_q[r * 64 + dq * 4] = *(const float4*)(Qbase + (size_t)r * DD + dq * 4);
    }

    const int Lmax = q0 + TQ;
    const int nch  = (Lmax + CK - 1) / CK;

    const int ldq = tid & 15;            // dk quad (chunk loads)
    const int ljj = tid >> 4;            // key sub-row 0..15

    // ---------- Phase 1: scores ----------
    const int kg = w & 3;                // key group (32 keys)
    const int rh = (w >> 2) * 4;         // row half (rows rh..rh+3)

    for (int c = 0; c < nch; c++) {
        #pragma unroll
        for (int jt = 0; jt < 8; jt++) {
            int j = ljj + jt * 16;
            *(float4*)&s_kv[j * 68 + ldq * 4] =
                *(const float4*)(Kbase + (size_t)(c * CK + j) * DD + ldq * 4);
        }
        __syncthreads();

        const int jbase = c * CK + kg * 32;
        if (jbase < Lmax) {
            const float* kp = &s_kv[(kg * 32 + lane) * 68];
            unsigned long long acc2[4] = {0ull, 0ull, 0ull, 0ull};
            #pragma unroll
            for (int dq = 0; dq < 16; dq++) {
                ulonglong2 k2 = *(const ulonglong2*)(kp + dq * 4);
                #pragma unroll
                for (int r = 0; r < 4; r++) {
                    ulonglong2 q2 = *(const ulonglong2*)&s_q[(rh + r) * 64 + dq * 4];
                    ffma2(acc2[r], k2.x, q2.x);
                    ffma2(acc2[r], k2.y, q2.y);
                }
            }
            #pragma unroll
            for (int r = 0; r < 4; r++) {
                float2 f = unpack2(acc2[r]);
                s_sc[(rh + r) * 1024 + jbase + lane] = (f.x + f.y) * 0.125f;
            }
        }
        __syncthreads();
    }

    // ---------- Phase 2: per-row softmax / cumsum / decay / softmax ----------
    {
        float* row = s_sc + w * 1024;
        float* cum = s_cum + w * 1024;
        const int rl = q0 + w;
        const int Lr = rl + 1;

        float m1 = -3.0e38f;
        #pragma unroll
        for (int i = 0; i < 32; i++) {
            int j = i * 32 + lane;
            if (j < Lr) m1 = fmaxf(m1, row[j]);
        }
        m1 = warpReduceMax(m1);

        float tot;
        {
            float carry = 0.f;
            #pragma unroll
            for (int i = 0; i < 32; i++) {
                int j = i * 32 + lane;
                float x = (j < Lr) ? __expf(row[j] - m1) : 0.f;
                #pragma unroll
                for (int d = 1; d < 32; d <<= 1) {
                    float y = __shfl_up_sync(0xffffffffu, x, d);
                    if (lane >= d) x += y;
                }
                cum[j] = carry + x;
                carry += __shfl_sync(0xffffffffu, x, 31);
            }
            tot = carry;
        }

        const float gh = gammas[h];
        const float gv = -log1pf(__expf(gh));
        const float rtot = 1.0f / tot;

        float m2 = -3.0e38f;
        #pragma unroll
        for (int i = 0; i < 32; i++) {
            int j = i * 32 + lane;
            if (j < Lr) {
                float s = row[j];
                float rem = fmaxf((tot - cum[j]) * rtot, 0.f);
                float dist = sqrtf(rem * (float)(rl - j));
                float em = fminf(fmaxf(__expf(dist * gv), 1e-5f), 1e5f);
                float v = s * em;
                row[j] = v;
                m2 = fmaxf(m2, v);
            }
        }
        m2 = warpReduceMax(m2);

        float psum = 0.f;
        #pragma unroll
        for (int i = 0; i < 32; i++) {
            int j = i * 32 + lane;
            float e = 0.f;
            if (j < Lr) {
                e = __expf(row[j] - m2);
                psum += e;
            }
            row[j] = e;                 // zero beyond Lr for phase 3
        }
        psum = warpReduceSum(psum);
        if (lane == 0) s_rsum[w] = 1.0f / psum;
    }
    __syncthreads();

    // ---------- Phase 3: O = P @ V ----------
    const int rg  = lane >> 4;           // row group 0/1
    const int dkq = lane & 15;           // dk quad

    unsigned long long acc2[4][2] = {};
    for (int c = 0; c < nch; c++) {
        #pragma unroll
        for (int jt = 0; jt < 8; jt++) {
            int j = ljj + jt * 16;
            *(float4*)&s_kv[j * 68 + ldq * 4] =
                *(const float4*)(Vbase + (size_t)(c * CK + j) * DD + ldq * 4);
        }
        __syncthreads();

        const int sbase = w * 16;
        #pragma unroll
        for (int jj = 0; jj < 16; jj++) {
            int j  = sbase + jj;
            int gj = c * CK + j;
            ulonglong2 v2 = *(const ulonglong2*)&s_kv[j * 68 + dkq * 4];
            #pragma unroll
            for (int r = 0; r < 4; r++) {
                float pv = s_sc[(rg * 4 + r) * 1024 + gj];
                unsigned long long p2 = pack2(pv, pv);
                ffma2(acc2[r][0], p2, v2.x);
                ffma2(acc2[r][1], p2, v2.y);
            }
        }
        __syncthreads();
    }

    #pragma unroll
    for (int r = 0; r < 4; r++) {
        float2 f0 = unpack2(acc2[r][0]);
        float2 f1 = unpack2(acc2[r][1]);
        float4 o4;
        o4.x = f0.x; o4.y = f0.y; o4.z = f1.x; o4.w = f1.y;
        *(float4*)&s_part[((w * 8) + rg * 4 + r) * 64 + dkq * 4] = o4;
    }
    __syncthreads();

    // reduce 8 partials, scale, write out
    float* Obase = g_bufO[st] + ((size_t)(b * SS + q0)) * DD + h * DKK;
    #pragma unroll
    for (int rr = 0; rr < 2; rr++) {
        int e = tid + rr * 256;          // 0..511
        int r = e >> 6, d = e & 63;
        float s = 0.f;
        #pragma unroll
        for (int s8 = 0; s8 < 8; s8++) s += s_part[((s8 * 8) + r) * 64 + d];
        Obase[(size_t)r * DD + d] = s * s_rsum[r];
    }
}

// ---------------- launch ----------------
extern "C" void kernel_launch(void* const* d_in, const int* in_sizes, int n_in,
                              void* d_out, int out_size) {
    const float* q_m  = (const float*)d_in[0];
    const float* q_c  = (const float*)d_in[1];
    const float* k_m  = (const float*)d_in[2];
    const float* k_c  = (const float*)d_in[3];
    const float* v_m  = (const float*)d_in[4];
    const float* v_c  = (const float*)d_in[5];
    const float* Wk_m = (const float*)d_in[6];
    const float* bk_m = (const float*)d_in[7];
    const float* Wk_c = (const float*)d_in[8];
    const float* bk_c = (const float*)d_in[9];
    const float* Wv_m = (const float*)d_in[10];
    const float* bv_m = (const float*)d_in[11];
    const float* Wv_c = (const float*)d_in[12];
    const float* bv_c = (const float*)d_in[13];
    const float* Wo_m = (const float*)d_in[14];
    const float* bo_m = (const float*)d_in[15];
    const float* Wo_c = (const float*)d_in[16];
    const float* bo_c = (const float*)d_in[17];
    const float* gam  = (const float*)d_in[18];
    float* out = (float*)d_out;

    float *bQ, *bK, *bV, *bO;
    cudaGetSymbolAddress((void**)&bQ, g_bufQ);
    cudaGetSymbolAddress((void**)&bK, g_bufK);
    cudaGetSymbolAddress((void**)&bV, g_bufV);
    cudaGetSymbolAddress((void**)&bO, g_bufO);

    static bool attr_set = false;
    if (!attr_set) {
        cudaFuncSetAttribute(attn_kernel, cudaFuncAttributeMaxDynamicSharedMemorySize,
                             SMEM_ATTN_FLOATS * 4);
        attr_set = true;
    }

    // 6 projection GEMMs in one launch (Q and K share Wk per stream)
    GB8 proj{};
    proj.g[0] = { q_m, Wk_m, bk_m, bQ };
    proj.g[1] = { k_m, Wk_m, bk_m, bK };
    proj.g[2] = { v_m, Wv_m, bv_m, bV };
    proj.g[3] = { q_c, Wk_c, bk_c, bQ + BSD };
    proj.g[4] = { k_c, Wk_c, bk_c, bK + BSD };
    proj.g[5] = { v_c, Wv_c, bv_c, bV + BSD };
    gemm_batch_kernel<<<dim3(512 / GN, 4096 / GM, 6), 256>>>(proj);

    // attention (both streams)
    attn_kernel<<<dim3(SS / TQ, BB * HH, 2), 256, SMEM_ATTN_FLOATS * 4>>>(gam);

    // 2 output GEMMs in one launch
    GB8 outp{};
    outp.g[0] = { bO,       Wo_m, bo_m, out };
    outp.g[1] = { bO + BSD, Wo_c, bo_c, out + BSD };
    gemm_batch_kernel<<<dim3(512 / GN, 4096 / GM, 2), 256>>>(outp);
}

// round 5
// speedup vs baseline: 1.0081x; 1.0081x over previous
#include <cuda_runtime.h>
#include <cstdint>

// Problem constants
#define BB 4
#define SS 1024
#define DD 512
#define HH 8
#define DKK 64
#define BSD (BB*SS*DD)   // 2097152
#define TQ 8             // query rows per attention CTA
#define CK 128           // keys per attention chunk
#define RS 1056          // padded score row stride (1024 + 32)

// ---------------- scratch (device globals; no allocation) ----------------
__device__ float g_bufQ[2][BSD];
__device__ float g_bufK[2][BSD];
__device__ float g_bufV[2][BSD];
__device__ float g_bufO[2][BSD];

// ---------------- batched GEMM: C = A[4096,512] @ W[512,512] + bias ----------------
struct GB  { const float* A; const float* W; const float* bias; float* C; };
struct GB8 { GB g[8]; };

#define GM 64
#define GN 64
#define GK 16

__global__ __launch_bounds__(256)
void gemm_batch_kernel(GB8 args) {
    const GB p = args.g[blockIdx.z];

    __shared__ __align__(16) float As[2][GK][68];   // k-major, padded
    __shared__ __align__(16) float Ws[2][GK][GN];

    const int tid = threadIdx.x;
    const int tx = tid & 15;         // n quad
    const int ty = tid >> 4;         // m quad
    const int m0 = blockIdx.y * GM;
    const int n0 = blockIdx.x * GN;

    const int lm  = tid >> 2;        // A row 0..63
    const int lkq = tid & 3;         // A k-quad 0..3
    const int lk  = tid >> 4;        // W row 0..15
    const int lnq = tid & 15;        // W n-quad

    const float* Aptr = p.A + (size_t)(m0 + lm) * 512 + lkq * 4;
    const float* Wptr = p.W + (size_t)lk * 512 + n0 + lnq * 4;

    float4 a4 = *(const float4*)(Aptr);
    float4 w4 = *(const float4*)(Wptr);
    As[0][lkq * 4 + 0][lm] = a4.x;
    As[0][lkq * 4 + 1][lm] = a4.y;
    As[0][lkq * 4 + 2][lm] = a4.z;
    As[0][lkq * 4 + 3][lm] = a4.w;
    *(float4*)&Ws[0][lk][lnq * 4] = w4;
    __syncthreads();

    float acc[4][4] = {};
    int buf = 0;

    for (int k0 = 0; k0 < 512; k0 += GK) {
        const bool more = (k0 + GK) < 512;
        if (more) {
            a4 = *(const float4*)(Aptr + k0 + GK);
            w4 = *(const float4*)(Wptr + (size_t)(k0 + GK) * 512);
        }
        #pragma unroll
        for (int k = 0; k < GK; k++) {
            float4 av = *(const float4*)&As[buf][k][ty * 4];
            float4 wv = *(const float4*)&Ws[buf][k][tx * 4];
            acc[0][0] += av.x * wv.x; acc[0][1] += av.x * wv.y;
            acc[0][2] += av.x * wv.z; acc[0][3] += av.x * wv.w;
            acc[1][0] += av.y * wv.x; acc[1][1] += av.y * wv.y;
            acc[1][2] += av.y * wv.z; acc[1][3] += av.y * wv.w;
            acc[2][0] += av.z * wv.x; acc[2][1] += av.z * wv.y;
            acc[2][2] += av.z * wv.z; acc[2][3] += av.z * wv.w;
            acc[3][0] += av.w * wv.x; acc[3][1] += av.w * wv.y;
            acc[3][2] += av.w * wv.z; acc[3][3] += av.w * wv.w;
        }
        if (more) {
            int nb = buf ^ 1;
            As[nb][lkq * 4 + 0][lm] = a4.x;
            As[nb][lkq * 4 + 1][lm] = a4.y;
            As[nb][lkq * 4 + 2][lm] = a4.z;
            As[nb][lkq * 4 + 3][lm] = a4.w;
            *(float4*)&Ws[nb][lk][lnq * 4] = w4;
        }
        __syncthreads();
        buf ^= 1;
    }

    float4 b4 = *(const float4*)(p.bias + n0 + tx * 4);
    #pragma unroll
    for (int i = 0; i < 4; i++) {
        float4 o;
        o.x = acc[i][0] + b4.x;
        o.y = acc[i][1] + b4.y;
        o.z = acc[i][2] + b4.z;
        o.w = acc[i][3] + b4.w;
        *(float4*)(p.C + (size_t)(m0 + ty * 4 + i) * 512 + n0 + tx * 4) = o;
    }
}

// ---------------- attention ----------------
__device__ __forceinline__ float warpReduceSum(float v) {
    #pragma unroll
    for (int o = 16; o > 0; o >>= 1) v += __shfl_xor_sync(0xffffffffu, v, o);
    return v;
}
__device__ __forceinline__ float warpReduceMax(float v) {
    #pragma unroll
    for (int o = 16; o > 0; o >>= 1) v = fmaxf(v, __shfl_xor_sync(0xffffffffu, v, o));
    return v;
}

// dynamic smem layout (floats):
//   s_sc   [8][1056]       8448   (padded: element j at offset j + (j>>5))
//   s_q    [8][64]          512
//   s_kv   [128][68]       8704
//   s_part [8][8][64]      4096
//   s_rsum [8]                8
#define OFF_Q    8448
#define OFF_KV   (OFF_Q + 512)
#define OFF_PART (OFF_KV + 8704)
#define OFF_RSUM (OFF_PART + 4096)
#define SMEM_ATTN_FLOATS (OFF_RSUM + 8)

__global__ __launch_bounds__(256, 2)
void attn_kernel(const float* __restrict__ gammas) {
    extern __shared__ float sm[];
    float* s_sc   = sm;               // [r*RS + j + (j>>5)]
    float* s_q    = sm + OFF_Q;       // [r*64 + d]
    float* s_kv   = sm + OFF_KV;      // [j*68 + d]
    float* s_part = sm + OFF_PART;    // [(s*8 + r)*64 + d]
    float* s_rsum = sm + OFF_RSUM;

    const int q0 = blockIdx.x * TQ;
    const int bh = blockIdx.y;
    const int b  = bh >> 3;
    const int h  = bh & 7;
    const int st = blockIdx.z;

    const int tid  = threadIdx.x;
    const int lane = tid & 31;
    const int w    = tid >> 5;          // warp 0..7

    const float* __restrict__ Qbase = g_bufQ[st] + ((size_t)(b * SS + q0)) * DD + h * DKK;
    const float* __restrict__ Kbase = g_bufK[st] + (size_t)b * SS * DD + h * DKK;
    const float* __restrict__ Vbase = g_bufV[st] + (size_t)b * SS * DD + h * DKK;

    // load Q tile (8x64)
    if (tid < 128) {
        int r = tid >> 4, dq = tid & 15;
        *(float4*)&s_q[r * 64 + dq * 4] = *(const float4*)(Qbase + (size_t)r * DD + dq * 4);
    }

    const int Lmax = q0 + TQ;
    const int nch  = (Lmax + CK - 1) / CK;

    const int ldq = tid & 15;            // dk quad (chunk loads)
    const int ljj = tid >> 4;            // key sub-row 0..15

    // ---------- Phase 1: scores ----------
    const int kg = w & 3;                // key group (32 keys)
    const int rh = (w >> 2) * 4;         // row half (rows rh..rh+3)

    for (int c = 0; c < nch; c++) {
        #pragma unroll
        for (int jt = 0; jt < 8; jt++) {
            int j = ljj + jt * 16;
            *(float4*)&s_kv[j * 68 + ldq * 4] =
                *(const float4*)(Kbase + (size_t)(c * CK + j) * DD + ldq * 4);
        }
        __syncthreads();

        const int jbase = c * CK + kg * 32;
        if (jbase < Lmax) {
            const int jp = jbase + (jbase >> 5) + lane;   // padded offset
            const float* kp = &s_kv[(kg * 32 + lane) * 68];
            float acc[4] = {};
            #pragma unroll
            for (int dq = 0; dq < 16; dq++) {
                float4 k4 = *(const float4*)(kp + dq * 4);
                #pragma unroll
                for (int r = 0; r < 4; r++) {
                    float4 q4 = *(const float4*)&s_q[(rh + r) * 64 + dq * 4];
                    acc[r] += k4.x * q4.x + k4.y * q4.y + k4.z * q4.z + k4.w * q4.w;
                }
            }
            #pragma unroll
            for (int r = 0; r < 4; r++)
                s_sc[(rh + r) * RS + jp] = acc[r] * 0.125f;
        }
        __syncthreads();
    }

    // ---------- Phase 2: per-row softmax / cumsum / decay / softmax ----------
    // Each lane owns contiguous keys [lane*32, lane*32+32) (padded base lane*33).
    {
        float* row = s_sc + w * RS;
        const int rl = q0 + w;
        const int Lr = rl + 1;
        const int jb = lane * 32;
        const int pb = lane * 33;

        float sreg[32];
        #pragma unroll
        for (int k = 0; k < 32; k++) sreg[k] = row[pb + k];

        float m1 = -3.0e38f;
        #pragma unroll
        for (int k = 0; k < 32; k++)
            if (jb + k < Lr) m1 = fmaxf(m1, sreg[k]);
        m1 = warpReduceMax(m1);

        float e[32];
        float segsum = 0.f;
        #pragma unroll
        for (int k = 0; k < 32; k++) {
            e[k] = (jb + k < Lr) ? __expf(sreg[k] - m1) : 0.f;
            segsum += e[k];
        }

        // warp inclusive scan of segment sums
        float incl = segsum;
        #pragma unroll
        for (int d = 1; d < 32; d <<= 1) {
            float y = __shfl_up_sync(0xffffffffu, incl, d);
            if (lane >= d) incl += y;
        }
        const float tot = __shfl_sync(0xffffffffu, incl, 31);
        float run = incl - segsum;       // exclusive prefix for this segment

        const float gh = gammas[h];
        const float gv = -log1pf(__expf(gh));
        const float rtot = 1.0f / tot;

        float m2 = -3.0e38f;
        #pragma unroll
        for (int k = 0; k < 32; k++) {
            run += e[k];                 // inclusive cumsum at j = jb+k
            if (jb + k < Lr) {
                float rem = fmaxf((tot - run) * rtot, 0.f);
                float dist = sqrtf(rem * (float)(rl - (jb + k)));
                float em = fminf(fmaxf(__expf(dist * gv), 1e-5f), 1e5f);
                float v = sreg[k] * em;
                sreg[k] = v;
                m2 = fmaxf(m2, v);
            }
        }
        m2 = warpReduceMax(m2);

        float psum = 0.f;
        #pragma unroll
        for (int k = 0; k < 32; k++) {
            float e2 = (jb + k < Lr) ? __expf(sreg[k] - m2) : 0.f;
            row[pb + k] = e2;            // zero beyond Lr for phase 3
            psum += e2;
        }
        psum = warpReduceSum(psum);
        if (lane == 0) s_rsum[w] = 1.0f / psum;
    }
    __syncthreads();

    // ---------- Phase 3: O = P @ V ----------
    const int rg  = lane >> 4;           // row group 0/1
    const int dkq = lane & 15;           // dk quad

    float4 acc4[4] = {};
    for (int c = 0; c < nch; c++) {
        #pragma unroll
        for (int jt = 0; jt < 8; jt++) {
            int j = ljj + jt * 16;
            *(float4*)&s_kv[j * 68 + ldq * 4] =
                *(const float4*)(Vbase + (size_t)(c * CK + j) * DD + ldq * 4);
        }
        __syncthreads();

        const int sbase = w * 16;
        #pragma unroll
        for (int jj = 0; jj < 16; jj++) {
            int j  = sbase + jj;
            int gj = c * CK + j;
            int pj = gj + (gj >> 5);
            float4 v4 = *(const float4*)&s_kv[j * 68 + dkq * 4];
            #pragma unroll
            for (int r = 0; r < 4; r++) {
                float pv = s_sc[(rg * 4 + r) * RS + pj];
                acc4[r].x += pv * v4.x;
                acc4[r].y += pv * v4.y;
                acc4[r].z += pv * v4.z;
                acc4[r].w += pv * v4.w;
            }
        }
        __syncthreads();
    }

    #pragma unroll
    for (int r = 0; r < 4; r++)
        *(float4*)&s_part[((w * 8) + rg * 4 + r) * 64 + dkq * 4] = acc4[r];
    __syncthreads();

    // reduce 8 partials, scale, write out
    float* Obase = g_bufO[st] + ((size_t)(b * SS + q0)) * DD + h * DKK;
    #pragma unroll
    for (int rr = 0; rr < 2; rr++) {
        int e = tid + rr * 256;          // 0..511
        int r = e >> 6, d = e & 63;
        float s = 0.f;
        #pragma unroll
        for (int s8 = 0; s8 < 8; s8++) s += s_part[((s8 * 8) + r) * 64 + d];
        Obase[(size_t)r * DD + d] = s * s_rsum[r];
    }
}

// ---------------- launch ----------------
extern "C" void kernel_launch(void* const* d_in, const int* in_sizes, int n_in,
                              void* d_out, int out_size) {
    const float* q_m  = (const float*)d_in[0];
    const float* q_c  = (const float*)d_in[1];
    const float* k_m  = (const float*)d_in[2];
    const float* k_c  = (const float*)d_in[3];
    const float* v_m  = (const float*)d_in[4];
    const float* v_c  = (const float*)d_in[5];
    const float* Wk_m = (const float*)d_in[6];
    const float* bk_m = (const float*)d_in[7];
    const float* Wk_c = (const float*)d_in[8];
    const float* bk_c = (const float*)d_in[9];
    const float* Wv_m = (const float*)d_in[10];
    const float* bv_m = (const float*)d_in[11];
    const float* Wv_c = (const float*)d_in[12];
    const float* bv_c = (const float*)d_in[13];
    const float* Wo_m = (const float*)d_in[14];
    const float* bo_m = (const float*)d_in[15];
    const float* Wo_c = (const float*)d_in[16];
    const float* bo_c = (const float*)d_in[17];
    const float* gam  = (const float*)d_in[18];
    float* out = (float*)d_out;

    float *bQ, *bK, *bV, *bO;
    cudaGetSymbolAddress((void**)&bQ, g_bufQ);
    cudaGetSymbolAddress((void**)&bK, g_bufK);
    cudaGetSymbolAddress((void**)&bV, g_bufV);
    cudaGetSymbolAddress((void**)&bO, g_bufO);

    static bool attr_set = false;
    if (!attr_set) {
        cudaFuncSetAttribute(attn_kernel, cudaFuncAttributeMaxDynamicSharedMemorySize,
                             SMEM_ATTN_FLOATS * 4);
        attr_set = true;
    }

    // 6 projection GEMMs in one launch (Q and K share Wk per stream)
    GB8 proj{};
    proj.g[0] = { q_m, Wk_m, bk_m, bQ };
    proj.g[1] = { k_m, Wk_m, bk_m, bK };
    proj.g[2] = { v_m, Wv_m, bv_m, bV };
    proj.g[3] = { q_c, Wk_c, bk_c, bQ + BSD };
    proj.g[4] = { k_c, Wk_c, bk_c, bK + BSD };
    proj.g[5] = { v_c, Wv_c, bv_c, bV + BSD };
    gemm_batch_kernel<<<dim3(512 / GN, 4096 / GM, 6), 256>>>(proj);

    // attention (both streams)
    attn_kernel<<<dim3(SS / TQ, BB * HH, 2), 256, SMEM_ATTN_FLOATS * 4>>>(gam);

    // 2 output GEMMs in one launch
    GB8 outp{};
    outp.g[0] = { bO,       Wo_m, bo_m, out };
    outp.g[1] = { bO + BSD, Wo_c, bo_c, out + BSD };
    gemm_batch_kernel<<<dim3(512 / GN, 4096 / GM, 2), 256>>>(outp);
}

// round 6
// speedup vs baseline: 1.4603x; 1.4485x over previous
#include <cuda_runtime.h>
#include <cstdint>

// Problem constants
#define BB 4
#define SS 1024
#define DD 512
#define HH 8
#define DKK 64
#define BSD (BB*SS*DD)   // 2097152
#define TQ 8             // query rows per attention CTA
#define CK 128           // keys per attention chunk

// ---------------- scratch (device globals; no allocation) ----------------
__device__ float g_bufQ[2][BSD];
__device__ float g_bufK[2][BSD];
__device__ float g_bufV[2][BSD];
__device__ float g_bufO[2][BSD];

// ---------------- tf32 tensor-core GEMM: C = A[4096,512] @ W[512,512] + bias --------
struct GB  { const float* A; const float* W; const float* bias; float* C; };
struct GB8 { GB g[8]; };

__device__ __forceinline__ unsigned cvt_tf32(float x) {
    unsigned r;
    asm("cvt.rna.tf32.f32 %0, %1;" : "=r"(r) : "f"(x));
    return r;
}

__device__ __forceinline__ void mma_tf32(float* c,
                                         unsigned a0, unsigned a1, unsigned a2, unsigned a3,
                                         unsigned b0, unsigned b1) {
    asm("mma.sync.aligned.m16n8k8.row.col.f32.tf32.tf32.f32 "
        "{%0,%1,%2,%3}, {%4,%5,%6,%7}, {%8,%9}, {%0,%1,%2,%3};"
        : "+f"(c[0]), "+f"(c[1]), "+f"(c[2]), "+f"(c[3])
        : "r"(a0), "r"(a1), "r"(a2), "r"(a3), "r"(b0), "r"(b1));
}

// CTA tile 128x128, K-tile 32. 8 warps: 2 (m) x 4 (n), warp tile 64x32.
__global__ __launch_bounds__(256)
void gemm_tc_kernel(GB8 args) {
    const GB p = args.g[blockIdx.z];

    __shared__ __align__(16) float As[128][36];   // [m][k], pad->conflict-free frags
    __shared__ __align__(16) float Ws[32][136];   // [k][n], pad->conflict-free frags

    const int tid  = threadIdx.x;
    const int lane = tid & 31;
    const int wid  = tid >> 5;
    const int wm0  = (wid & 1) * 64;
    const int wn0  = (wid >> 1) * 32;
    const int m0   = blockIdx.y * 128;
    const int n0   = blockIdx.x * 128;

    // loader mapping
    const int am = tid >> 3;            // A row 0..31 (+r*32)
    const int ak = (tid & 7) * 4;       // A k-quad base
    const int wk = tid >> 5;            // W row 0..7 (+r*8)
    const int wn = (tid & 31) * 4;      // W n-quad base

    const float* Ap = p.A + (size_t)(m0 + am) * 512 + ak;
    const float* Wp = p.W + (size_t)wk * 512 + n0 + wn;

    float4 aR[4], wR[4];
    #pragma unroll
    for (int r = 0; r < 4; r++) {
        aR[r] = *(const float4*)(Ap + (size_t)(r * 32) * 512);
        wR[r] = *(const float4*)(Wp + (size_t)(r * 8) * 512);
    }

    float acc[4][4][4];                 // [mt][nt][frag]
    #pragma unroll
    for (int i = 0; i < 4; i++)
        #pragma unroll
        for (int j = 0; j < 4; j++)
            #pragma unroll
            for (int u = 0; u < 4; u++) acc[i][j][u] = 0.f;

    for (int kt = 0; kt < 16; kt++) {
        // stage (tf32-rounded) tiles to smem
        #pragma unroll
        for (int r = 0; r < 4; r++) {
            float4 a = aR[r];
            a.x = __uint_as_float(cvt_tf32(a.x));
            a.y = __uint_as_float(cvt_tf32(a.y));
            a.z = __uint_as_float(cvt_tf32(a.z));
            a.w = __uint_as_float(cvt_tf32(a.w));
            *(float4*)&As[am + r * 32][ak] = a;
            float4 w = wR[r];
            w.x = __uint_as_float(cvt_tf32(w.x));
            w.y = __uint_as_float(cvt_tf32(w.y));
            w.z = __uint_as_float(cvt_tf32(w.z));
            w.w = __uint_as_float(cvt_tf32(w.w));
            *(float4*)&Ws[wk + r * 8][wn] = w;
        }
        __syncthreads();

        if (kt < 15) {
            const int ko = (kt + 1) * 32;
            #pragma unroll
            for (int r = 0; r < 4; r++) {
                aR[r] = *(const float4*)(Ap + (size_t)(r * 32) * 512 + ko);
                wR[r] = *(const float4*)(Wp + (size_t)(r * 8) * 512 + (size_t)ko * 512);
            }
        }

        #pragma unroll
        for (int ks = 0; ks < 4; ks++) {
            const int kk = ks * 8 + (lane & 3);
            unsigned b0[4], b1[4];
            #pragma unroll
            for (int tn = 0; tn < 4; tn++) {
                int n = wn0 + tn * 8 + (lane >> 2);
                b0[tn] = __float_as_uint(Ws[kk][n]);
                b1[tn] = __float_as_uint(Ws[kk + 4][n]);
            }
            #pragma unroll
            for (int tm = 0; tm < 4; tm++) {
                int m = wm0 + tm * 16 + (lane >> 2);
                unsigned a0 = __float_as_uint(As[m][kk]);
                unsigned a1 = __float_as_uint(As[m + 8][kk]);
                unsigned a2 = __float_as_uint(As[m][kk + 4]);
                unsigned a3 = __float_as_uint(As[m + 8][kk + 4]);
                #pragma unroll
                for (int tn = 0; tn < 4; tn++)
                    mma_tf32(acc[tm][tn], a0, a1, a2, a3, b0[tn], b1[tn]);
            }
        }
        __syncthreads();
    }

    // epilogue: bias + store
    const int cm = lane >> 2;
    const int cn = (lane & 3) * 2;
    #pragma unroll
    for (int tn = 0; tn < 4; tn++) {
        int n = n0 + wn0 + tn * 8 + cn;
        float2 bb = *(const float2*)(p.bias + n);
        #pragma unroll
        for (int tm = 0; tm < 4; tm++) {
            int m = m0 + wm0 + tm * 16 + cm;
            float2 o0, o1;
            o0.x = acc[tm][tn][0] + bb.x; o0.y = acc[tm][tn][1] + bb.y;
            o1.x = acc[tm][tn][2] + bb.x; o1.y = acc[tm][tn][3] + bb.y;
            *(float2*)(p.C + (size_t)m * 512 + n) = o0;
            *(float2*)(p.C + (size_t)(m + 8) * 512 + n) = o1;
        }
    }
}

// ---------------- attention (R3 version — best measured) ----------------
__device__ __forceinline__ float warpReduceSum(float v) {
    #pragma unroll
    for (int o = 16; o > 0; o >>= 1) v += __shfl_xor_sync(0xffffffffu, v, o);
    return v;
}
__device__ __forceinline__ float warpReduceMax(float v) {
    #pragma unroll
    for (int o = 16; o > 0; o >>= 1) v = fmaxf(v, __shfl_xor_sync(0xffffffffu, v, o));
    return v;
}

// dynamic smem layout (floats):
//   s_sc   [8][1024]       8192
//   s_q    [8][64]          512
//   s_kv   [128][68]       8704
//   s_part [8][8][64]      4096
//   s_rsum [8]                8
#define SMEM_ATTN_FLOATS (8192 + 512 + 8704 + 4096 + 8)

__global__ __launch_bounds__(256)
void attn_kernel(const float* __restrict__ gammas) {
    extern __shared__ float sm[];
    float* s_sc   = sm;               // [r*1024 + j]
    float* s_q    = sm + 8192;        // [r*64 + d]
    float* s_kv   = sm + 8704;        // [j*68 + d]
    float* s_part = sm + 17408;       // [(s*8 + r)*64 + d]
    float* s_rsum = sm + 21504;

    const int q0 = blockIdx.x * TQ;
    const int bh = blockIdx.y;
    const int b  = bh >> 3;
    const int h  = bh & 7;
    const int st = blockIdx.z;

    const int tid  = threadIdx.x;
    const int lane = tid & 31;
    const int w    = tid >> 5;          // warp 0..7

    const float* __restrict__ Qbase = g_bufQ[st] + ((size_t)(b * SS + q0)) * DD + h * DKK;
    const float* __restrict__ Kbase = g_bufK[st] + (size_t)b * SS * DD + h * DKK;
    const float* __restrict__ Vbase = g_bufV[st] + (size_t)b * SS * DD + h * DKK;

    // load Q tile (8x64)
    if (tid < 128) {
        int r = tid >> 4, dq = tid & 15;
        *(float4*)&s_q[r * 64 + dq * 4] = *(const float4*)(Qbase + (size_t)r * DD + dq * 4);
    }

    const int Lmax = q0 + TQ;
    const int nch  = (Lmax + CK - 1) / CK;

    const int ldq = tid & 15;            // dk quad (chunk loads)
    const int ljj = tid >> 4;            // key sub-row 0..15

    // ---------- Phase 1: scores ----------
    const int kg = w & 3;                // key group (32 keys)
    const int rh = (w >> 2) * 4;         // row half (rows rh..rh+3)

    for (int c = 0; c < nch; c++) {
        #pragma unroll
        for (int jt = 0; jt < 8; jt++) {
            int j = ljj + jt * 16;
            *(float4*)&s_kv[j * 68 + ldq * 4] =
                *(const float4*)(Kbase + (size_t)(c * CK + j) * DD + ldq * 4);
        }
        __syncthreads();

        const int jbase = c * CK + kg * 32;
        if (jbase < Lmax) {
            const float* kp = &s_kv[(kg * 32 + lane) * 68];
            float acc[4] = {};
            #pragma unroll
            for (int dq = 0; dq < 16; dq++) {
                float4 k4 = *(const float4*)(kp + dq * 4);
                #pragma unroll
                for (int r = 0; r < 4; r++) {
                    float4 q4 = *(const float4*)&s_q[(rh + r) * 64 + dq * 4];
                    acc[r] += k4.x * q4.x + k4.y * q4.y + k4.z * q4.z + k4.w * q4.w;
                }
            }
            #pragma unroll
            for (int r = 0; r < 4; r++)
                s_sc[(rh + r) * 1024 + jbase + lane] = acc[r] * 0.125f;
        }
        __syncthreads();
    }

    // ---------- Phase 2: per-row softmax / cumsum / decay / softmax ----------
    {
        float* row = s_sc + w * 1024;
        const int rl = q0 + w;
        const int Lr = rl + 1;

        float m1 = -3.0e38f;
        #pragma unroll
        for (int i = 0; i < 32; i++) {
            int j = i * 32 + lane;
            if (j < Lr) m1 = fmaxf(m1, row[j]);
        }
        m1 = warpReduceMax(m1);

        float c_reg[32];
        float tot;
        {
            float carry = 0.f;
            #pragma unroll
            for (int i = 0; i < 32; i++) {
                int j = i * 32 + lane;
                float x = (j < Lr) ? __expf(row[j] - m1) : 0.f;
                #pragma unroll
                for (int d = 1; d < 32; d <<= 1) {
                    float y = __shfl_up_sync(0xffffffffu, x, d);
                    if (lane >= d) x += y;
                }
                c_reg[i] = carry + x;
                carry += __shfl_sync(0xffffffffu, x, 31);
            }
            tot = carry;
        }

        const float gh = gammas[h];
        const float gv = -log1pf(__expf(gh));
        const float rtot = 1.0f / tot;

        float m2 = -3.0e38f;
        #pragma unroll
        for (int i = 0; i < 32; i++) {
            int j = i * 32 + lane;
            if (j < Lr) {
                float s = row[j];
                float rem = fmaxf((tot - c_reg[i]) * rtot, 0.f);
                float dist = sqrtf(rem * (float)(rl - j));
                float em = fminf(fmaxf(__expf(dist * gv), 1e-5f), 1e5f);
                float v = s * em;
                row[j] = v;
                m2 = fmaxf(m2, v);
            }
        }
        m2 = warpReduceMax(m2);

        float psum = 0.f;
        #pragma unroll
        for (int i = 0; i < 32; i++) {
            int j = i * 32 + lane;
            float e = 0.f;
            if (j < Lr) {
                e = __expf(row[j] - m2);
                psum += e;
            }
            row[j] = e;                 // zero beyond Lr for phase 3
        }
        psum = warpReduceSum(psum);
        if (lane == 0) s_rsum[w] = 1.0f / psum;
    }
    __syncthreads();

    // ---------- Phase 3: O = P @ V ----------
    const int rg  = lane >> 4;           // row group 0/1
    const int dkq = lane & 15;           // dk quad

    float4 acc4[4] = {};
    for (int c = 0; c < nch; c++) {
        #pragma unroll
        for (int jt = 0; jt < 8; jt++) {
            int j = ljj + jt * 16;
            *(float4*)&s_kv[j * 68 + ldq * 4] =
                *(const float4*)(Vbase + (size_t)(c * CK + j) * DD + ldq * 4);
        }
        __syncthreads();

        const int sbase = w * 16;
        #pragma unroll
        for (int jj = 0; jj < 16; jj++) {
            int j  = sbase + jj;
            int gj = c * CK + j;
            float4 v4 = *(const float4*)&s_kv[j * 68 + dkq * 4];
            #pragma unroll
            for (int r = 0; r < 4; r++) {
                float pv = s_sc[(rg * 4 + r) * 1024 + gj];
                acc4[r].x += pv * v4.x;
                acc4[r].y += pv * v4.y;
                acc4[r].z += pv * v4.z;
                acc4[r].w += pv * v4.w;
            }
        }
        __syncthreads();
    }

    #pragma unroll
    for (int r = 0; r < 4; r++)
        *(float4*)&s_part[((w * 8) + rg * 4 + r) * 64 + dkq * 4] = acc4[r];
    __syncthreads();

    // reduce 8 partials, scale, write out
    float* Obase = g_bufO[st] + ((size_t)(b * SS + q0)) * DD + h * DKK;
    #pragma unroll
    for (int rr = 0; rr < 2; rr++) {
        int e = tid + rr * 256;          // 0..511
        int r = e >> 6, d = e & 63;
        float s = 0.f;
        #pragma unroll
        for (int s8 = 0; s8 < 8; s8++) s += s_part[((s8 * 8) + r) * 64 + d];
        Obase[(size_t)r * DD + d] = s * s_rsum[r];
    }
}

// ---------------- launch ----------------
extern "C" void kernel_launch(void* const* d_in, const int* in_sizes, int n_in,
                              void* d_out, int out_size) {
    const float* q_m  = (const float*)d_in[0];
    const float* q_c  = (const float*)d_in[1];
    const float* k_m  = (const float*)d_in[2];
    const float* k_c  = (const float*)d_in[3];
    const float* v_m  = (const float*)d_in[4];
    const float* v_c  = (const float*)d_in[5];
    const float* Wk_m = (const float*)d_in[6];
    const float* bk_m = (const float*)d_in[7];
    const float* Wk_c = (const float*)d_in[8];
    const float* bk_c = (const float*)d_in[9];
    const float* Wv_m = (const float*)d_in[10];
    const float* bv_m = (const float*)d_in[11];
    const float* Wv_c = (const float*)d_in[12];
    const float* bv_c = (const float*)d_in[13];
    const float* Wo_m = (const float*)d_in[14];
    const float* bo_m = (const float*)d_in[15];
    const float* Wo_c = (const float*)d_in[16];
    const float* bo_c = (const float*)d_in[17];
    const float* gam  = (const float*)d_in[18];
    float* out = (float*)d_out;

    float *bQ, *bK, *bV, *bO;
    cudaGetSymbolAddress((void**)&bQ, g_bufQ);
    cudaGetSymbolAddress((void**)&bK, g_bufK);
    cudaGetSymbolAddress((void**)&bV, g_bufV);
    cudaGetSymbolAddress((void**)&bO, g_bufO);

    cudaFuncSetAttribute(attn_kernel, cudaFuncAttributeMaxDynamicSharedMemorySize,
                         SMEM_ATTN_FLOATS * 4);

    // 6 projection GEMMs in one launch (Q and K share Wk per stream)
    GB8 proj{};
    proj.g[0] = { q_m, Wk_m, bk_m, bQ };
    proj.g[1] = { k_m, Wk_m, bk_m, bK };
    proj.g[2] = { v_m, Wv_m, bv_m, bV };
    proj.g[3] = { q_c, Wk_c, bk_c, bQ + BSD };
    proj.g[4] = { k_c, Wk_c, bk_c, bK + BSD };
    proj.g[5] = { v_c, Wv_c, bv_c, bV + BSD };
    gemm_tc_kernel<<<dim3(512 / 128, 4096 / 128, 6), 256>>>(proj);

    // attention (both streams)
    attn_kernel<<<dim3(SS / TQ, BB * HH, 2), 256, SMEM_ATTN_FLOATS * 4>>>(gam);

    // 2 output GEMMs in one launch
    GB8 outp{};
    outp.g[0] = { bO,       Wo_m, bo_m, out };
    outp.g[1] = { bO + BSD, Wo_c, bo_c, out + BSD };
    gemm_tc_kernel<<<dim3(512 / 128, 4096 / 128, 2), 256>>>(outp);
}

// round 7
// speedup vs baseline: 1.7144x; 1.1740x over previous
#include <cuda_runtime.h>
#include <cstdint>

// Problem constants
#define BB 4
#define SS 1024
#define DD 512
#define HH 8
#define DKK 64
#define BSD (BB*SS*DD)   // 2097152
#define TQ 16            // query rows per attention CTA
#define RS2 1028         // padded score row stride

// ---------------- scratch (device globals; no allocation) ----------------
__device__ float g_bufQ[2][BSD];
__device__ float g_bufK[2][BSD];
__device__ float g_bufV[2][BSD];
__device__ float g_bufO[2][BSD];

// ---------------- tf32 helpers ----------------
__device__ __forceinline__ float cvt_tf32f(float x) {
    unsigned r;
    asm("cvt.rna.tf32.f32 %0, %1;" : "=r"(r) : "f"(x));
    return __uint_as_float(r);
}
__device__ __forceinline__ void mma_tf32(float* c,
                                         unsigned a0, unsigned a1, unsigned a2, unsigned a3,
                                         unsigned b0, unsigned b1) {
    asm("mma.sync.aligned.m16n8k8.row.col.f32.tf32.tf32.f32 "
        "{%0,%1,%2,%3}, {%4,%5,%6,%7}, {%8,%9}, {%0,%1,%2,%3};"
        : "+f"(c[0]), "+f"(c[1]), "+f"(c[2]), "+f"(c[3])
        : "r"(a0), "r"(a1), "r"(a2), "r"(a3), "r"(b0), "r"(b1));
}

// ---------------- tf32 tensor-core GEMM (unchanged from R6) ----------------
struct GB  { const float* A; const float* W; const float* bias; float* C; };
struct GB8 { GB g[8]; };

__device__ __forceinline__ unsigned cvt_tf32(float x) {
    unsigned r;
    asm("cvt.rna.tf32.f32 %0, %1;" : "=r"(r) : "f"(x));
    return r;
}

__global__ __launch_bounds__(256)
void gemm_tc_kernel(GB8 args) {
    const GB p = args.g[blockIdx.z];

    __shared__ __align__(16) float As[128][36];
    __shared__ __align__(16) float Ws[32][136];

    const int tid  = threadIdx.x;
    const int lane = tid & 31;
    const int wid  = tid >> 5;
    const int wm0  = (wid & 1) * 64;
    const int wn0  = (wid >> 1) * 32;
    const int m0   = blockIdx.y * 128;
    const int n0   = blockIdx.x * 128;

    const int am = tid >> 3;
    const int ak = (tid & 7) * 4;
    const int wk = tid >> 5;
    const int wn = (tid & 31) * 4;

    const float* Ap = p.A + (size_t)(m0 + am) * 512 + ak;
    const float* Wp = p.W + (size_t)wk * 512 + n0 + wn;

    float4 aR[4], wR[4];
    #pragma unroll
    for (int r = 0; r < 4; r++) {
        aR[r] = *(const float4*)(Ap + (size_t)(r * 32) * 512);
        wR[r] = *(const float4*)(Wp + (size_t)(r * 8) * 512);
    }

    float acc[4][4][4];
    #pragma unroll
    for (int i = 0; i < 4; i++)
        #pragma unroll
        for (int j = 0; j < 4; j++)
            #pragma unroll
            for (int u = 0; u < 4; u++) acc[i][j][u] = 0.f;

    for (int kt = 0; kt < 16; kt++) {
        #pragma unroll
        for (int r = 0; r < 4; r++) {
            float4 a = aR[r];
            a.x = __uint_as_float(cvt_tf32(a.x));
            a.y = __uint_as_float(cvt_tf32(a.y));
            a.z = __uint_as_float(cvt_tf32(a.z));
            a.w = __uint_as_float(cvt_tf32(a.w));
            *(float4*)&As[am + r * 32][ak] = a;
            float4 w = wR[r];
            w.x = __uint_as_float(cvt_tf32(w.x));
            w.y = __uint_as_float(cvt_tf32(w.y));
            w.z = __uint_as_float(cvt_tf32(w.z));
            w.w = __uint_as_float(cvt_tf32(w.w));
            *(float4*)&Ws[wk + r * 8][wn] = w;
        }
        __syncthreads();

        if (kt < 15) {
            const int ko = (kt + 1) * 32;
            #pragma unroll
            for (int r = 0; r < 4; r++) {
                aR[r] = *(const float4*)(Ap + (size_t)(r * 32) * 512 + ko);
                wR[r] = *(const float4*)(Wp + (size_t)(r * 8) * 512 + (size_t)ko * 512);
            }
        }

        #pragma unroll
        for (int ks = 0; ks < 4; ks++) {
            const int kk = ks * 8 + (lane & 3);
            unsigned b0[4], b1[4];
            #pragma unroll
            for (int tn = 0; tn < 4; tn++) {
                int n = wn0 + tn * 8 + (lane >> 2);
                b0[tn] = __float_as_uint(Ws[kk][n]);
                b1[tn] = __float_as_uint(Ws[kk + 4][n]);
            }
            #pragma unroll
            for (int tm = 0; tm < 4; tm++) {
                int m = wm0 + tm * 16 + (lane >> 2);
                unsigned a0 = __float_as_uint(As[m][kk]);
                unsigned a1 = __float_as_uint(As[m + 8][kk]);
                unsigned a2 = __float_as_uint(As[m][kk + 4]);
                unsigned a3 = __float_as_uint(As[m + 8][kk + 4]);
                #pragma unroll
                for (int tn = 0; tn < 4; tn++)
                    mma_tf32(acc[tm][tn], a0, a1, a2, a3, b0[tn], b1[tn]);
            }
        }
        __syncthreads();
    }

    const int cm = lane >> 2;
    const int cn = (lane & 3) * 2;
    #pragma unroll
    for (int tn = 0; tn < 4; tn++) {
        int n = n0 + wn0 + tn * 8 + cn;
        float2 bb = *(const float2*)(p.bias + n);
        #pragma unroll
        for (int tm = 0; tm < 4; tm++) {
            int m = m0 + wm0 + tm * 16 + cm;
            float2 o0, o1;
            o0.x = acc[tm][tn][0] + bb.x; o0.y = acc[tm][tn][1] + bb.y;
            o1.x = acc[tm][tn][2] + bb.x; o1.y = acc[tm][tn][3] + bb.y;
            *(float2*)(p.C + (size_t)m * 512 + n) = o0;
            *(float2*)(p.C + (size_t)(m + 8) * 512 + n) = o1;
        }
    }
}

// ---------------- attention (tensor-core, split-tf32) ----------------
__device__ __forceinline__ float warpReduceSum(float v) {
    #pragma unroll
    for (int o = 16; o > 0; o >>= 1) v += __shfl_xor_sync(0xffffffffu, v, o);
    return v;
}
__device__ __forceinline__ float warpReduceMax(float v) {
    #pragma unroll
    for (int o = 16; o > 0; o >>= 1) v = fmaxf(v, __shfl_xor_sync(0xffffffffu, v, o));
    return v;
}

// dynamic smem layout (floats)
#define OFF_QH 16448                    // s_sc = 16*1028
#define OFF_QL (OFF_QH + 16*76)
#define OFF_KH (OFF_QL + 16*76)
#define OFF_KL (OFF_KH + 64*76)
#define OFF_RS (OFF_KL + 64*76)
#define ATTN_SM_FLOATS (OFF_RS + 16)    // 28624 floats = 114496 B

__global__ __launch_bounds__(256, 2)
void attn_kernel(const float* __restrict__ gammas) {
    extern __shared__ float sm[];
    float* s_sc = sm;                   // [16][1028]
    float* s_qh = sm + OFF_QH;          // [16][76]
    float* s_ql = sm + OFF_QL;
    float* s_kh = sm + OFF_KH;          // [64][76]  (K then V)
    float* s_kl = sm + OFF_KL;
    float* s_rs = sm + OFF_RS;          // [16]

    const int q0 = blockIdx.x * TQ;
    const int bh = blockIdx.y;
    const int b  = bh >> 3;
    const int h  = bh & 7;
    const int st = blockIdx.z;

    const int tid  = threadIdx.x;
    const int lane = tid & 31;
    const int w    = tid >> 5;          // warp 0..7
    const int fr   = lane >> 2;         // fragment row 0..7
    const int fc   = lane & 3;          // fragment col 0..3

    const float* __restrict__ Qbase = g_bufQ[st] + ((size_t)(b * SS + q0)) * DD + h * DKK;
    const float* __restrict__ Kbase = g_bufK[st] + (size_t)b * SS * DD + h * DKK;
    const float* __restrict__ Vbase = g_bufV[st] + (size_t)b * SS * DD + h * DKK;

    // ---- stage Q (16x64) as tf32 hi/lo ----
    {
        int r = tid >> 4, qd = (tid & 15) * 4;
        float4 q = *(const float4*)(Qbase + (size_t)r * DD + qd);
        float4 hi, lo;
        hi.x = cvt_tf32f(q.x); lo.x = cvt_tf32f(q.x - hi.x);
        hi.y = cvt_tf32f(q.y); lo.y = cvt_tf32f(q.y - hi.y);
        hi.z = cvt_tf32f(q.z); lo.z = cvt_tf32f(q.z - hi.z);
        hi.w = cvt_tf32f(q.w); lo.w = cvt_tf32f(q.w - hi.w);
        *(float4*)&s_qh[r * 76 + qd] = hi;
        *(float4*)&s_ql[r * 76 + qd] = lo;
    }
    __syncthreads();

    // ---- cache Q fragments in registers ----
    unsigned qfh[8][4], qfl[8][4];
    #pragma unroll
    for (int kt = 0; kt < 8; kt++) {
        int kk = kt * 8 + fc;
        qfh[kt][0] = __float_as_uint(s_qh[fr * 76 + kk]);
        qfh[kt][1] = __float_as_uint(s_qh[(fr + 8) * 76 + kk]);
        qfh[kt][2] = __float_as_uint(s_qh[fr * 76 + kk + 4]);
        qfh[kt][3] = __float_as_uint(s_qh[(fr + 8) * 76 + kk + 4]);
        qfl[kt][0] = __float_as_uint(s_ql[fr * 76 + kk]);
        qfl[kt][1] = __float_as_uint(s_ql[(fr + 8) * 76 + kk]);
        qfl[kt][2] = __float_as_uint(s_ql[fr * 76 + kk + 4]);
        qfl[kt][3] = __float_as_uint(s_ql[(fr + 8) * 76 + kk + 4]);
    }

    const int Lmax = q0 + TQ;
    const int nch  = (Lmax + 63) >> 6;

    const int lr = tid >> 4;             // loader row 0..15
    const int lq = (tid & 15) * 4;       // loader col quad

    // ---------- Phase 1: S = Q @ K^T (split-tf32 MMA) ----------
    for (int c = 0; c < nch; c++) {
        #pragma unroll
        for (int i = 0; i < 4; i++) {
            int row = lr + i * 16;
            float4 k = *(const float4*)(Kbase + (size_t)(c * 64 + row) * DD + lq);
            float4 hi, lo;
            hi.x = cvt_tf32f(k.x); lo.x = cvt_tf32f(k.x - hi.x);
            hi.y = cvt_tf32f(k.y); lo.y = cvt_tf32f(k.y - hi.y);
            hi.z = cvt_tf32f(k.z); lo.z = cvt_tf32f(k.z - hi.z);
            hi.w = cvt_tf32f(k.w); lo.w = cvt_tf32f(k.w - hi.w);
            *(float4*)&s_kh[row * 76 + lq] = hi;
            *(float4*)&s_kl[row * 76 + lq] = lo;
        }
        __syncthreads();

        float cc[4] = {0.f, 0.f, 0.f, 0.f};
        const int nb = w * 8;            // this warp's 8 keys within chunk
        #pragma unroll
        for (int kt = 0; kt < 8; kt++) {
            int kk = kt * 8 + fc;
            int ja = (nb + fr) * 76;
            unsigned bh0 = __float_as_uint(s_kh[ja + kk]);
            unsigned bh1 = __float_as_uint(s_kh[ja + kk + 4]);
            unsigned bl0 = __float_as_uint(s_kl[ja + kk]);
            unsigned bl1 = __float_as_uint(s_kl[ja + kk + 4]);
            mma_tf32(cc, qfh[kt][0], qfh[kt][1], qfh[kt][2], qfh[kt][3], bh0, bh1);
            mma_tf32(cc, qfh[kt][0], qfh[kt][1], qfh[kt][2], qfh[kt][3], bl0, bl1);
            mma_tf32(cc, qfl[kt][0], qfl[kt][1], qfl[kt][2], qfl[kt][3], bh0, bh1);
        }
        int jcol = c * 64 + nb + fc * 2;
        float2 s0, s1;
        s0.x = cc[0] * 0.125f; s0.y = cc[1] * 0.125f;
        s1.x = cc[2] * 0.125f; s1.y = cc[3] * 0.125f;
        *(float2*)&s_sc[fr * RS2 + jcol] = s0;
        *(float2*)&s_sc[(fr + 8) * RS2 + jcol] = s1;
        __syncthreads();
    }

    // ---------- Phase 2: per-row softmax / cumsum / decay / softmax ----------
    const float gh = gammas[h];
    const float gv = -log1pf(__expf(gh));
    #pragma unroll
    for (int rr = 0; rr < 2; rr++) {
        int rloc = w + rr * 8;
        float* row = s_sc + rloc * RS2;
        const int rl = q0 + rloc;
        const int Lr = rl + 1;

        float m1 = -3.0e38f;
        #pragma unroll
        for (int i = 0; i < 32; i++) {
            int j = i * 32 + lane;
            if (j < Lr) m1 = fmaxf(m1, row[j]);
        }
        m1 = warpReduceMax(m1);

        float c_reg[32];
        float tot;
        {
            float carry = 0.f;
            #pragma unroll
            for (int i = 0; i < 32; i++) {
                int j = i * 32 + lane;
                float x = (j < Lr) ? __expf(row[j] - m1) : 0.f;
                #pragma unroll
                for (int d = 1; d < 32; d <<= 1) {
                    float y = __shfl_up_sync(0xffffffffu, x, d);
                    if (lane >= d) x += y;
                }
                c_reg[i] = carry + x;
                carry += __shfl_sync(0xffffffffu, x, 31);
            }
            tot = carry;
        }

        const float rtot = 1.0f / tot;
        float m2 = -3.0e38f;
        #pragma unroll
        for (int i = 0; i < 32; i++) {
            int j = i * 32 + lane;
            if (j < Lr) {
                float s = row[j];
                float rem = fmaxf((tot - c_reg[i]) * rtot, 0.f);
                float dist = sqrtf(rem * (float)(rl - j));
                float em = fminf(fmaxf(__expf(dist * gv), 1e-5f), 1e5f);
                float v = s * em;
                row[j] = v;
                m2 = fmaxf(m2, v);
            }
        }
        m2 = warpReduceMax(m2);

        float psum = 0.f;
        #pragma unroll
        for (int i = 0; i < 32; i++) {
            int j = i * 32 + lane;
            float e = 0.f;
            if (j < Lr) {
                e = __expf(row[j] - m2);
                psum += e;
            }
            row[j] = e;                  // zero beyond Lr for phase 3
        }
        psum = warpReduceSum(psum);
        if (lane == 0) s_rs[rloc] = 1.0f / psum;
    }
    __syncthreads();

    // ---------- Phase 3: O = P @ V (split-tf32 MMA) ----------
    float oc[4] = {0.f, 0.f, 0.f, 0.f};
    const int vb = w * 8 + fr;           // this warp's d-column (n index)
    for (int c = 0; c < nch; c++) {
        #pragma unroll
        for (int i = 0; i < 4; i++) {
            int row = lr + i * 16;
            float4 v = *(const float4*)(Vbase + (size_t)(c * 64 + row) * DD + lq);
            float4 hi, lo;
            hi.x = cvt_tf32f(v.x); lo.x = cvt_tf32f(v.x - hi.x);
            hi.y = cvt_tf32f(v.y); lo.y = cvt_tf32f(v.y - hi.y);
            hi.z = cvt_tf32f(v.z); lo.z = cvt_tf32f(v.z - hi.z);
            hi.w = cvt_tf32f(v.w); lo.w = cvt_tf32f(v.w - hi.w);
            *(float4*)&s_kh[row * 76 + lq] = hi;
            *(float4*)&s_kl[row * 76 + lq] = lo;
        }
        __syncthreads();

        #pragma unroll
        for (int kt = 0; kt < 8; kt++) {
            int kcol = c * 64 + kt * 8 + fc;
            float a0 = s_sc[fr * RS2 + kcol];
            float a1 = s_sc[(fr + 8) * RS2 + kcol];
            float a2 = s_sc[fr * RS2 + kcol + 4];
            float a3 = s_sc[(fr + 8) * RS2 + kcol + 4];
            float h0 = cvt_tf32f(a0), l0 = cvt_tf32f(a0 - h0);
            float h1 = cvt_tf32f(a1), l1 = cvt_tf32f(a1 - h1);
            float h2 = cvt_tf32f(a2), l2 = cvt_tf32f(a2 - h2);
            float h3 = cvt_tf32f(a3), l3 = cvt_tf32f(a3 - h3);

            int ka = (kt * 8 + fc) * 76;
            unsigned bh0 = __float_as_uint(s_kh[ka + vb]);
            unsigned bh1 = __float_as_uint(s_kh[ka + 4 * 76 + vb]);
            unsigned bl0 = __float_as_uint(s_kl[ka + vb]);
            unsigned bl1 = __float_as_uint(s_kl[ka + 4 * 76 + vb]);

            mma_tf32(oc, __float_as_uint(h0), __float_as_uint(h1),
                         __float_as_uint(h2), __float_as_uint(h3), bh0, bh1);
            mma_tf32(oc, __float_as_uint(h0), __float_as_uint(h1),
                         __float_as_uint(h2), __float_as_uint(h3), bl0, bl1);
            mma_tf32(oc, __float_as_uint(l0), __float_as_uint(l1),
                         __float_as_uint(l2), __float_as_uint(l3), bh0, bh1);
        }
        __syncthreads();
    }

    // epilogue: scale by 1/sum, write out
    float* Obase = g_bufO[st] + ((size_t)(b * SS + q0)) * DD + h * DKK;
    float rs0 = s_rs[fr], rs1 = s_rs[fr + 8];
    int dcol = w * 8 + fc * 2;
    float2 o0, o1;
    o0.x = oc[0] * rs0; o0.y = oc[1] * rs0;
    o1.x = oc[2] * rs1; o1.y = oc[3] * rs1;
    *(float2*)(Obase + (size_t)fr * DD + dcol) = o0;
    *(float2*)(Obase + (size_t)(fr + 8) * DD + dcol) = o1;
}

// ---------------- launch ----------------
extern "C" void kernel_launch(void* const* d_in, const int* in_sizes, int n_in,
                              void* d_out, int out_size) {
    const float* q_m  = (const float*)d_in[0];
    const float* q_c  = (const float*)d_in[1];
    const float* k_m  = (const float*)d_in[2];
    const float* k_c  = (const float*)d_in[3];
    const float* v_m  = (const float*)d_in[4];
    const float* v_c  = (const float*)d_in[5];
    const float* Wk_m = (const float*)d_in[6];
    const float* bk_m = (const float*)d_in[7];
    const float* Wk_c = (const float*)d_in[8];
    const float* bk_c = (const float*)d_in[9];
    const float* Wv_m = (const float*)d_in[10];
    const float* bv_m = (const float*)d_in[11];
    const float* Wv_c = (const float*)d_in[12];
    const float* bv_c = (const float*)d_in[13];
    const float* Wo_m = (const float*)d_in[14];
    const float* bo_m = (const float*)d_in[15];
    const float* Wo_c = (const float*)d_in[16];
    const float* bo_c = (const float*)d_in[17];
    const float* gam  = (const float*)d_in[18];
    float* out = (float*)d_out;

    float *bQ, *bK, *bV, *bO;
    cudaGetSymbolAddress((void**)&bQ, g_bufQ);
    cudaGetSymbolAddress((void**)&bK, g_bufK);
    cudaGetSymbolAddress((void**)&bV, g_bufV);
    cudaGetSymbolAddress((void**)&bO, g_bufO);

    cudaFuncSetAttribute(attn_kernel, cudaFuncAttributeMaxDynamicSharedMemorySize,
                         ATTN_SM_FLOATS * 4);

    // 6 projection GEMMs in one launch (Q and K share Wk per stream)
    GB8 proj{};
    proj.g[0] = { q_m, Wk_m, bk_m, bQ };
    proj.g[1] = { k_m, Wk_m, bk_m, bK };
    proj.g[2] = { v_m, Wv_m, bv_m, bV };
    proj.g[3] = { q_c, Wk_c, bk_c, bQ + BSD };
    proj.g[4] = { k_c, Wk_c, bk_c, bK + BSD };
    proj.g[5] = { v_c, Wv_c, bv_c, bV + BSD };
    gemm_tc_kernel<<<dim3(512 / 128, 4096 / 128, 6), 256>>>(proj);

    // attention (both streams)
    attn_kernel<<<dim3(SS / TQ, BB * HH, 2), 256, ATTN_SM_FLOATS * 4>>>(gam);

    // 2 output GEMMs in one launch
    GB8 outp{};
    outp.g[0] = { bO,       Wo_m, bo_m, out };
    outp.g[1] = { bO + BSD, Wo_c, bo_c, out + BSD };
    gemm_tc_kernel<<<dim3(512 / 128, 4096 / 128, 2), 256>>>(outp);
}

// round 8
// speedup vs baseline: 1.8386x; 1.0725x over previous
#include <cuda_runtime.h>
#include <cstdint>

// Problem constants
#define BB 4
#define SS 1024
#define DD 512
#define HH 8
#define DKK 64
#define BSD (BB*SS*DD)   // 2097152
#define TQ 16            // query rows per attention CTA
#define RS2 1028         // padded score row stride

// ---------------- scratch (device globals; no allocation) ----------------
__device__ float g_bufQ[2][BSD];
__device__ float g_bufK[2][BSD];
__device__ float g_bufV[2][BSD];
__device__ float g_bufO[2][BSD];

// ---------------- tf32 helpers ----------------
__device__ __forceinline__ float cvt_tf32f(float x) {
    unsigned r;
    asm("cvt.rna.tf32.f32 %0, %1;" : "=r"(r) : "f"(x));
    return __uint_as_float(r);
}
__device__ __forceinline__ void mma_tf32(float* c,
                                         unsigned a0, unsigned a1, unsigned a2, unsigned a3,
                                         unsigned b0, unsigned b1) {
    asm("mma.sync.aligned.m16n8k8.row.col.f32.tf32.tf32.f32 "
        "{%0,%1,%2,%3}, {%4,%5,%6,%7}, {%8,%9}, {%0,%1,%2,%3};"
        : "+f"(c[0]), "+f"(c[1]), "+f"(c[2]), "+f"(c[3])
        : "r"(a0), "r"(a1), "r"(a2), "r"(a3), "r"(b0), "r"(b1));
}

// ---------------- tf32 tensor-core GEMM (unchanged from R6) ----------------
struct GB  { const float* A; const float* W; const float* bias; float* C; };
struct GB8 { GB g[8]; };

__device__ __forceinline__ unsigned cvt_tf32(float x) {
    unsigned r;
    asm("cvt.rna.tf32.f32 %0, %1;" : "=r"(r) : "f"(x));
    return r;
}

__global__ __launch_bounds__(256)
void gemm_tc_kernel(GB8 args) {
    const GB p = args.g[blockIdx.z];

    __shared__ __align__(16) float As[128][36];
    __shared__ __align__(16) float Ws[32][136];

    const int tid  = threadIdx.x;
    const int lane = tid & 31;
    const int wid  = tid >> 5;
    const int wm0  = (wid & 1) * 64;
    const int wn0  = (wid >> 1) * 32;
    const int m0   = blockIdx.y * 128;
    const int n0   = blockIdx.x * 128;

    const int am = tid >> 3;
    const int ak = (tid & 7) * 4;
    const int wk = tid >> 5;
    const int wn = (tid & 31) * 4;

    const float* Ap = p.A + (size_t)(m0 + am) * 512 + ak;
    const float* Wp = p.W + (size_t)wk * 512 + n0 + wn;

    float4 aR[4], wR[4];
    #pragma unroll
    for (int r = 0; r < 4; r++) {
        aR[r] = *(const float4*)(Ap + (size_t)(r * 32) * 512);
        wR[r] = *(const float4*)(Wp + (size_t)(r * 8) * 512);
    }

    float acc[4][4][4];
    #pragma unroll
    for (int i = 0; i < 4; i++)
        #pragma unroll
        for (int j = 0; j < 4; j++)
            #pragma unroll
            for (int u = 0; u < 4; u++) acc[i][j][u] = 0.f;

    for (int kt = 0; kt < 16; kt++) {
        #pragma unroll
        for (int r = 0; r < 4; r++) {
            float4 a = aR[r];
            a.x = __uint_as_float(cvt_tf32(a.x));
            a.y = __uint_as_float(cvt_tf32(a.y));
            a.z = __uint_as_float(cvt_tf32(a.z));
            a.w = __uint_as_float(cvt_tf32(a.w));
            *(float4*)&As[am + r * 32][ak] = a;
            float4 w = wR[r];
            w.x = __uint_as_float(cvt_tf32(w.x));
            w.y = __uint_as_float(cvt_tf32(w.y));
            w.z = __uint_as_float(cvt_tf32(w.z));
            w.w = __uint_as_float(cvt_tf32(w.w));
            *(float4*)&Ws[wk + r * 8][wn] = w;
        }
        __syncthreads();

        if (kt < 15) {
            const int ko = (kt + 1) * 32;
            #pragma unroll
            for (int r = 0; r < 4; r++) {
                aR[r] = *(const float4*)(Ap + (size_t)(r * 32) * 512 + ko);
                wR[r] = *(const float4*)(Wp + (size_t)(r * 8) * 512 + (size_t)ko * 512);
            }
        }

        #pragma unroll
        for (int ks = 0; ks < 4; ks++) {
            const int kk = ks * 8 + (lane & 3);
            unsigned b0[4], b1[4];
            #pragma unroll
            for (int tn = 0; tn < 4; tn++) {
                int n = wn0 + tn * 8 + (lane >> 2);
                b0[tn] = __float_as_uint(Ws[kk][n]);
                b1[tn] = __float_as_uint(Ws[kk + 4][n]);
            }
            #pragma unroll
            for (int tm = 0; tm < 4; tm++) {
                int m = wm0 + tm * 16 + (lane >> 2);
                unsigned a0 = __float_as_uint(As[m][kk]);
                unsigned a1 = __float_as_uint(As[m + 8][kk]);
                unsigned a2 = __float_as_uint(As[m][kk + 4]);
                unsigned a3 = __float_as_uint(As[m + 8][kk + 4]);
                #pragma unroll
                for (int tn = 0; tn < 4; tn++)
                    mma_tf32(acc[tm][tn], a0, a1, a2, a3, b0[tn], b1[tn]);
            }
        }
        __syncthreads();
    }

    const int cm = lane >> 2;
    const int cn = (lane & 3) * 2;
    #pragma unroll
    for (int tn = 0; tn < 4; tn++) {
        int n = n0 + wn0 + tn * 8 + cn;
        float2 bb = *(const float2*)(p.bias + n);
        #pragma unroll
        for (int tm = 0; tm < 4; tm++) {
            int m = m0 + wm0 + tm * 16 + cm;
            float2 o0, o1;
            o0.x = acc[tm][tn][0] + bb.x; o0.y = acc[tm][tn][1] + bb.y;
            o1.x = acc[tm][tn][2] + bb.x; o1.y = acc[tm][tn][3] + bb.y;
            *(float2*)(p.C + (size_t)m * 512 + n) = o0;
            *(float2*)(p.C + (size_t)(m + 8) * 512 + n) = o1;
        }
    }
}

// ---------------- attention (tensor-core, split-tf32) ----------------
__device__ __forceinline__ float warpReduceSum(float v) {
    #pragma unroll
    for (int o = 16; o > 0; o >>= 1) v += __shfl_xor_sync(0xffffffffu, v, o);
    return v;
}
__device__ __forceinline__ float warpReduceMax(float v) {
    #pragma unroll
    for (int o = 16; o > 0; o >>= 1) v = fmaxf(v, __shfl_xor_sync(0xffffffffu, v, o));
    return v;
}

// dynamic smem layout (floats)  —  Q is staged through the K buffers (aliased)
#define OFF_KH 16448                    // s_sc = 16*1028
#define OFF_KL (OFF_KH + 64*76)
#define OFF_RS (OFF_KL + 64*76)
#define ATTN_SM_FLOATS (OFF_RS + 16)    // 26192 floats = 104768 B  -> 2 CTA/SM

__global__ __launch_bounds__(256, 2)
void attn_kernel(const float* __restrict__ gammas) {
    extern __shared__ float sm[];
    float* s_sc = sm;                   // [16][1028]
    float* s_kh = sm + OFF_KH;          // [64][76]  (Q-hi staging, then K/V)
    float* s_kl = sm + OFF_KL;          // [64][76]  (Q-lo staging, then K-lo)
    float* s_rs = sm + OFF_RS;          // [16]

    const int q0 = blockIdx.x * TQ;
    const int bh = blockIdx.y;
    const int b  = bh >> 3;
    const int h  = bh & 7;
    const int st = blockIdx.z;

    const int tid  = threadIdx.x;
    const int lane = tid & 31;
    const int w    = tid >> 5;          // warp 0..7
    const int fr   = lane >> 2;         // fragment row 0..7
    const int fc   = lane & 3;          // fragment col 0..3

    const float* __restrict__ Qbase = g_bufQ[st] + ((size_t)(b * SS + q0)) * DD + h * DKK;
    const float* __restrict__ Kbase = g_bufK[st] + (size_t)b * SS * DD + h * DKK;
    const float* __restrict__ Vbase = g_bufV[st] + (size_t)b * SS * DD + h * DKK;

    // ---- stage Q (16x64) as tf32 hi/lo into the K buffers (aliased) ----
    {
        int r = tid >> 4, qd = (tid & 15) * 4;
        float4 q = *(const float4*)(Qbase + (size_t)r * DD + qd);
        float4 hi, lo;
        hi.x = cvt_tf32f(q.x); lo.x = cvt_tf32f(q.x - hi.x);
        hi.y = cvt_tf32f(q.y); lo.y = cvt_tf32f(q.y - hi.y);
        hi.z = cvt_tf32f(q.z); lo.z = cvt_tf32f(q.z - hi.z);
        hi.w = cvt_tf32f(q.w); lo.w = cvt_tf32f(q.w - hi.w);
        *(float4*)&s_kh[r * 76 + qd] = hi;
        *(float4*)&s_kl[r * 76 + qd] = lo;
    }
    __syncthreads();

    // ---- cache Q fragments in registers ----
    unsigned qfh[8][4], qfl[8][4];
    #pragma unroll
    for (int kt = 0; kt < 8; kt++) {
        int kk = kt * 8 + fc;
        qfh[kt][0] = __float_as_uint(s_kh[fr * 76 + kk]);
        qfh[kt][1] = __float_as_uint(s_kh[(fr + 8) * 76 + kk]);
        qfh[kt][2] = __float_as_uint(s_kh[fr * 76 + kk + 4]);
        qfh[kt][3] = __float_as_uint(s_kh[(fr + 8) * 76 + kk + 4]);
        qfl[kt][0] = __float_as_uint(s_kl[fr * 76 + kk]);
        qfl[kt][1] = __float_as_uint(s_kl[(fr + 8) * 76 + kk]);
        qfl[kt][2] = __float_as_uint(s_kl[fr * 76 + kk + 4]);
        qfl[kt][3] = __float_as_uint(s_kl[(fr + 8) * 76 + kk + 4]);
    }
    __syncthreads();                    // Q staging done; buffers free for K

    const int Lmax = q0 + TQ;
    const int nch  = (Lmax + 63) >> 6;

    const int lr = tid >> 4;             // loader row 0..15
    const int lq = (tid & 15) * 4;       // loader col quad

    // ---------- Phase 1: S = Q @ K^T (split-tf32, 3 MMA) ----------
    for (int c = 0; c < nch; c++) {
        #pragma unroll
        for (int i = 0; i < 4; i++) {
            int row = lr + i * 16;
            float4 k = *(const float4*)(Kbase + (size_t)(c * 64 + row) * DD + lq);
            float4 hi, lo;
            hi.x = cvt_tf32f(k.x); lo.x = cvt_tf32f(k.x - hi.x);
            hi.y = cvt_tf32f(k.y); lo.y = cvt_tf32f(k.y - hi.y);
            hi.z = cvt_tf32f(k.z); lo.z = cvt_tf32f(k.z - hi.z);
            hi.w = cvt_tf32f(k.w); lo.w = cvt_tf32f(k.w - hi.w);
            *(float4*)&s_kh[row * 76 + lq] = hi;
            *(float4*)&s_kl[row * 76 + lq] = lo;
        }
        __syncthreads();

        float cc[4] = {0.f, 0.f, 0.f, 0.f};
        const int nb = w * 8;            // this warp's 8 keys within chunk
        #pragma unroll
        for (int kt = 0; kt < 8; kt++) {
            int kk = kt * 8 + fc;
            int ja = (nb + fr) * 76;
            unsigned bh0 = __float_as_uint(s_kh[ja + kk]);
            unsigned bh1 = __float_as_uint(s_kh[ja + kk + 4]);
            unsigned bl0 = __float_as_uint(s_kl[ja + kk]);
            unsigned bl1 = __float_as_uint(s_kl[ja + kk + 4]);
            mma_tf32(cc, qfh[kt][0], qfh[kt][1], qfh[kt][2], qfh[kt][3], bh0, bh1);
            mma_tf32(cc, qfh[kt][0], qfh[kt][1], qfh[kt][2], qfh[kt][3], bl0, bl1);
            mma_tf32(cc, qfl[kt][0], qfl[kt][1], qfl[kt][2], qfl[kt][3], bh0, bh1);
        }
        int jcol = c * 64 + nb + fc * 2;
        float2 s0, s1;
        s0.x = cc[0] * 0.125f; s0.y = cc[1] * 0.125f;
        s1.x = cc[2] * 0.125f; s1.y = cc[3] * 0.125f;
        *(float2*)&s_sc[fr * RS2 + jcol] = s0;
        *(float2*)&s_sc[(fr + 8) * RS2 + jcol] = s1;
        __syncthreads();
    }

    // ---------- Phase 2: per-row softmax / cumsum / decay / softmax ----------
    const float gh = gammas[h];
    const float gv = -log1pf(__expf(gh));
    #pragma unroll
    for (int rr = 0; rr < 2; rr++) {
        int rloc = w + rr * 8;
        float* row = s_sc + rloc * RS2;
        const int rl = q0 + rloc;
        const int Lr = rl + 1;

        float m1 = -3.0e38f;
        #pragma unroll
        for (int i = 0; i < 32; i++) {
            int j = i * 32 + lane;
            if (j < Lr) m1 = fmaxf(m1, row[j]);
        }
        m1 = warpReduceMax(m1);

        float c_reg[32];
        float tot;
        {
            float carry = 0.f;
            #pragma unroll
            for (int i = 0; i < 32; i++) {
                int j = i * 32 + lane;
                float x = (j < Lr) ? __expf(row[j] - m1) : 0.f;
                #pragma unroll
                for (int d = 1; d < 32; d <<= 1) {
                    float y = __shfl_up_sync(0xffffffffu, x, d);
                    if (lane >= d) x += y;
                }
                c_reg[i] = carry + x;
                carry += __shfl_sync(0xffffffffu, x, 31);
            }
            tot = carry;
        }

        const float rtot = 1.0f / tot;
        float m2 = -3.0e38f;
        #pragma unroll
        for (int i = 0; i < 32; i++) {
            int j = i * 32 + lane;
            if (j < Lr) {
                float s = row[j];
                float rem = fmaxf((tot - c_reg[i]) * rtot, 0.f);
                float dist = sqrtf(rem * (float)(rl - j));
                float em = fminf(fmaxf(__expf(dist * gv), 1e-5f), 1e5f);
                float v = s * em;
                row[j] = v;
                m2 = fmaxf(m2, v);
            }
        }
        m2 = warpReduceMax(m2);

        float psum = 0.f;
        #pragma unroll
        for (int i = 0; i < 32; i++) {
            int j = i * 32 + lane;
            float e = 0.f;
            if (j < Lr) {
                e = __expf(row[j] - m2);
                psum += e;
            }
            row[j] = e;                  // zero beyond Lr for phase 3
        }
        psum = warpReduceSum(psum);
        if (lane == 0) s_rs[rloc] = 1.0f / psum;
    }
    __syncthreads();

    // ---------- Phase 3: O = P @ V (P split, V tf32-hi: 2 MMA) ----------
    float oc[4] = {0.f, 0.f, 0.f, 0.f};
    const int vb = w * 8 + fr;           // this warp's d-column (n index)
    for (int c = 0; c < nch; c++) {
        #pragma unroll
        for (int i = 0; i < 4; i++) {
            int row = lr + i * 16;
            float4 v = *(const float4*)(Vbase + (size_t)(c * 64 + row) * DD + lq);
            float4 hi;
            hi.x = cvt_tf32f(v.x);
            hi.y = cvt_tf32f(v.y);
            hi.z = cvt_tf32f(v.z);
            hi.w = cvt_tf32f(v.w);
            *(float4*)&s_kh[row * 76 + lq] = hi;
        }
        __syncthreads();

        #pragma unroll
        for (int kt = 0; kt < 8; kt++) {
            int kcol = c * 64 + kt * 8 + fc;
            float a0 = s_sc[fr * RS2 + kcol];
            float a1 = s_sc[(fr + 8) * RS2 + kcol];
            float a2 = s_sc[fr * RS2 + kcol + 4];
            float a3 = s_sc[(fr + 8) * RS2 + kcol + 4];
            float h0 = cvt_tf32f(a0), l0 = cvt_tf32f(a0 - h0);
            float h1 = cvt_tf32f(a1), l1 = cvt_tf32f(a1 - h1);
            float h2 = cvt_tf32f(a2), l2 = cvt_tf32f(a2 - h2);
            float h3 = cvt_tf32f(a3), l3 = cvt_tf32f(a3 - h3);

            int ka = (kt * 8 + fc) * 76;
            unsigned bh0 = __float_as_uint(s_kh[ka + vb]);
            unsigned bh1 = __float_as_uint(s_kh[ka + 4 * 76 + vb]);

            mma_tf32(oc, __float_as_uint(h0), __float_as_uint(h1),
                         __float_as_uint(h2), __float_as_uint(h3), bh0, bh1);
            mma_tf32(oc, __float_as_uint(l0), __float_as_uint(l1),
                         __float_as_uint(l2), __float_as_uint(l3), bh0, bh1);
        }
        __syncthreads();
    }

    // epilogue: scale by 1/sum, write out
    float* Obase = g_bufO[st] + ((size_t)(b * SS + q0)) * DD + h * DKK;
    float rs0 = s_rs[fr], rs1 = s_rs[fr + 8];
    int dcol = w * 8 + fc * 2;
    float2 o0, o1;
    o0.x = oc[0] * rs0; o0.y = oc[1] * rs0;
    o1.x = oc[2] * rs1; o1.y = oc[3] * rs1;
    *(float2*)(Obase + (size_t)fr * DD + dcol) = o0;
    *(float2*)(Obase + (size_t)(fr + 8) * DD + dcol) = o1;
}

// ---------------- launch ----------------
extern "C" void kernel_launch(void* const* d_in, const int* in_sizes, int n_in,
                              void* d_out, int out_size) {
    const float* q_m  = (const float*)d_in[0];
    const float* q_c  = (const float*)d_in[1];
    const float* k_m  = (const float*)d_in[2];
    const float* k_c  = (const float*)d_in[3];
    const float* v_m  = (const float*)d_in[4];
    const float* v_c  = (const float*)d_in[5];
    const float* Wk_m = (const float*)d_in[6];
    const float* bk_m = (const float*)d_in[7];
    const float* Wk_c = (const float*)d_in[8];
    const float* bk_c = (const float*)d_in[9];
    const float* Wv_m = (const float*)d_in[10];
    const float* bv_m = (const float*)d_in[11];
    const float* Wv_c = (const float*)d_in[12];
    const float* bv_c = (const float*)d_in[13];
    const float* Wo_m = (const float*)d_in[14];
    const float* bo_m = (const float*)d_in[15];
    const float* Wo_c = (const float*)d_in[16];
    const float* bo_c = (const float*)d_in[17];
    const float* gam  = (const float*)d_in[18];
    float* out = (float*)d_out;

    float *bQ, *bK, *bV, *bO;
    cudaGetSymbolAddress((void**)&bQ, g_bufQ);
    cudaGetSymbolAddress((void**)&bK, g_bufK);
    cudaGetSymbolAddress((void**)&bV, g_bufV);
    cudaGetSymbolAddress((void**)&bO, g_bufO);

    cudaFuncSetAttribute(attn_kernel, cudaFuncAttributeMaxDynamicSharedMemorySize,
                         ATTN_SM_FLOATS * 4);

    // 6 projection GEMMs in one launch (Q and K share Wk per stream)
    GB8 proj{};
    proj.g[0] = { q_m, Wk_m, bk_m, bQ };
    proj.g[1] = { k_m, Wk_m, bk_m, bK };
    proj.g[2] = { v_m, Wv_m, bv_m, bV };
    proj.g[3] = { q_c, Wk_c, bk_c, bQ + BSD };
    proj.g[4] = { k_c, Wk_c, bk_c, bK + BSD };
    proj.g[5] = { v_c, Wv_c, bv_c, bV + BSD };
    gemm_tc_kernel<<<dim3(512 / 128, 4096 / 128, 6), 256>>>(proj);

    // attention (both streams)
    attn_kernel<<<dim3(SS / TQ, BB * HH, 2), 256, ATTN_SM_FLOATS * 4>>>(gam);

    // 2 output GEMMs in one launch
    GB8 outp{};
    outp.g[0] = { bO,       Wo_m, bo_m, out };
    outp.g[1] = { bO + BSD, Wo_c, bo_c, out + BSD };
    gemm_tc_kernel<<<dim3(512 / 128, 4096 / 128, 2), 256>>>(outp);
}